// round 13
// baseline (speedup 1.0000x reference)
#include <cuda_runtime.h>

#define NB 16          // batch
#define NBOX 256       // boxes

// ---------------- device scratch (no allocations allowed) ----------------
__device__ __align__(16) float g_mask0[NB * 80 * 80];
__device__ __align__(16) float g_mask1[NB * 40 * 40];
__device__ __align__(16) float g_mask2[NB * 20 * 20];
// [0..2] = sum(mask) per level, [3..5] = sum((m*(p-t))^2) per level
__device__ double g_acc[6];

// ---------------- helpers ----------------
__device__ __forceinline__ float block_reduce_sum(float v) {
    __shared__ float s[32];
    int lane = threadIdx.x & 31;
    int wid  = threadIdx.x >> 5;
    #pragma unroll
    for (int o = 16; o; o >>= 1) v += __shfl_down_sync(0xffffffffu, v, o);
    if (lane == 0) s[wid] = v;
    __syncthreads();
    int nw = (blockDim.x + 31) >> 5;
    if (wid == 0) {
        v = (lane < nw) ? s[lane] : 0.f;
        #pragma unroll
        for (int o = 16; o; o >>= 1) v += __shfl_down_sync(0xffffffffu, v, o);
    }
    return v;
}

__global__ void init_kernel() {
    if (threadIdx.x < 6) g_acc[threadIdx.x] = 0.0;
}

// ---------------- mask kernel ----------------
// grid: (NB, ceil(S*S/256)), block: 256
template <int S>
__global__ void mask_kernel(const float* __restrict__ bboxes,
                            const int*   __restrict__ batch_idx,
                            float* __restrict__ mask, int lvl) {
    __shared__ int   s_cnt;
    __shared__ float s_xc[NBOX], s_yc[NBOX], s_iw[NBOX], s_ih[NBOX];
    __shared__ int   s_xl[NBOX], s_xr[NBOX], s_yt[NBOX], s_yd[NBOX];

    const int b = blockIdx.x;
    if (threadIdx.x == 0) s_cnt = 0;
    __syncthreads();

    // compact this image's boxes into shared, precomputing gaussian params
    for (int i = threadIdx.x; i < NBOX; i += blockDim.x) {
        if (batch_idx[i] == b) {
            int j = atomicAdd(&s_cnt, 1);
            float4 bb = reinterpret_cast<const float4*>(bboxes)[i];
            int xc = (int)floorf(bb.x * (float)S);
            int yc = (int)floorf(bb.y * (float)S);
            int w  = (int)floorf(bb.z * (float)S);
            int h  = (int)floorf(bb.w * (float)S);
            int xl = max(xc - w / 2, 0);
            int xr = min(xc + w / 2, S - 1);
            int yt = max(yc - h / 2, 0);
            int yd = min(yc + h / 2, S - 1);
            float width  = (float)(xr - xl + 1);
            float height = (float)(yd - yt + 1);
            // STD=2: STD^2 * (width/2)^2 == width^2 exactly
            s_xc[j] = (float)xc;  s_yc[j] = (float)yc;
            s_iw[j] = 1.0f / (width * width);
            s_ih[j] = 1.0f / (height * height);
            s_xl[j] = xl; s_xr[j] = xr; s_yt[j] = yt; s_yd[j] = yd;
        }
    }
    __syncthreads();

    const int n   = s_cnt;
    const int pix = blockIdx.y * blockDim.x + threadIdx.x;
    float m = 0.0f;
    if (pix < S * S) {
        int y = pix / S;
        int x = pix - y * S;
        float fx = (float)x, fy = (float)y;
        for (int j = 0; j < n; j++) {
            if (x >= s_xl[j] && x <= s_xr[j] && y >= s_yt[j] && y <= s_yd[j]) {
                float dx = fx - s_xc[j];
                float dy = fy - s_yc[j];
                float e  = expf(-(dx * dx * s_iw[j] + dy * dy * s_ih[j]));
                m = fmaxf(m, e);
            }
        }
        mask[b * S * S + pix] = m;
    }
    __syncthreads();   // block_reduce uses shared; all threads must join
    float bs = block_reduce_sum(m);
    if (threadIdx.x == 0 && bs != 0.0f) atomicAdd(&g_acc[lvl], (double)bs);
}

// ---------------- streaming loss kernel ----------------
// One level per launch. pred/true are [B, C, S, S] float32; S*S % 4 == 0 and
// base pointers are cudaMalloc'd -> float4 views are safe.
template <int CSS, int SS>
__global__ void loss_kernel(const float4* __restrict__ p,
                            const float4* __restrict__ t,
                            const float*  __restrict__ mask,
                            int nvec, int lvl) {
    float acc = 0.0f;
    const int stride = gridDim.x * blockDim.x;
    for (int i = blockIdx.x * blockDim.x + threadIdx.x; i < nvec; i += stride) {
        float4 pv = p[i];
        float4 tv = t[i];
        int base = i * 4;
        int b    = base / CSS;              // const-div -> mul/shift
        int pix  = base % SS;               // SS divides CSS; pix % 4 == 0
        const float4 mv = *reinterpret_cast<const float4*>(&mask[b * SS + pix]);
        float d0 = mv.x * (pv.x - tv.x);
        float d1 = mv.y * (pv.y - tv.y);
        float d2 = mv.z * (pv.z - tv.z);
        float d3 = mv.w * (pv.w - tv.w);
        acc += d0 * d0 + d1 * d1 + d2 * d2 + d3 * d3;
    }
    float bs = block_reduce_sum(acc);
    if (threadIdx.x == 0) atomicAdd(&g_acc[3 + lvl], (double)bs);
}

__global__ void final_kernel(float* __restrict__ out) {
    if (threadIdx.x == 0) {
        const double C[3] = {128.0, 256.0, 512.0};
        double total = 0.0;
        #pragma unroll
        for (int l = 0; l < 3; l++)
            total += g_acc[3 + l] / (C[l] * g_acc[l]);
        out[0] = (float)(total / 3.0);
    }
}

// ---------------- launch ----------------
extern "C" void kernel_launch(void* const* d_in, const int* in_sizes, int n_in,
                              void* d_out, int out_size) {
    // metadata order (setup_inputs dict insertion order) is INTERLEAVED:
    // [0]=y_pred0 [1]=y_true0 [2]=y_pred1 [3]=y_true1 [4]=y_pred2 [5]=y_true2
    // [6]=bboxes  [7]=cls     [8]=batch_idx
    const float* p0 = (const float*)d_in[0];
    const float* t0 = (const float*)d_in[1];
    const float* p1 = (const float*)d_in[2];
    const float* t1 = (const float*)d_in[3];
    const float* p2 = (const float*)d_in[4];
    const float* t2 = (const float*)d_in[5];
    const float* bboxes = (const float*)d_in[6];
    // d_in[7] = cls (unused)
    const int* batch_idx = (const int*)d_in[8];

    float *m0, *m1, *m2;
    cudaGetSymbolAddress((void**)&m0, g_mask0);
    cudaGetSymbolAddress((void**)&m1, g_mask1);
    cudaGetSymbolAddress((void**)&m2, g_mask2);

    init_kernel<<<1, 32>>>();

    mask_kernel<80><<<dim3(NB, (80 * 80 + 255) / 256), 256>>>(bboxes, batch_idx, m0, 0);
    mask_kernel<40><<<dim3(NB, (40 * 40 + 255) / 256), 256>>>(bboxes, batch_idx, m1, 1);
    mask_kernel<20><<<dim3(NB, (20 * 20 + 255) / 256), 256>>>(bboxes, batch_idx, m2, 2);

    // grids are multiples of 148 SMs for even wave balance
    // level 0: 16*128*80*80 = 13,107,200 elems -> 3,276,800 vec4
    loss_kernel<128 * 6400, 6400><<<2072, 256>>>(
        (const float4*)p0, (const float4*)t0, m0, 3276800, 0);
    // level 1: 16*256*40*40 = 6,553,600 -> 1,638,400 vec4
    loss_kernel<256 * 1600, 1600><<<1036, 256>>>(
        (const float4*)p1, (const float4*)t1, m1, 1638400, 1);
    // level 2: 16*512*20*20 = 3,276,800 -> 819,200 vec4
    loss_kernel<512 * 400, 400><<<592, 256>>>(
        (const float4*)p2, (const float4*)t2, m2, 819200, 2);

    final_kernel<<<1, 32>>>((float*)d_out);
}

// round 15
// speedup vs baseline: 1.3738x; 1.3738x over previous
#include <cuda_runtime.h>

#define NB 16          // batch
#define NBOX 256       // boxes

// ---------------- device scratch (no allocations allowed) ----------------
__device__ __align__(16) float g_mask0[NB * 80 * 80];
__device__ __align__(16) float g_mask1[NB * 40 * 40];
__device__ __align__(16) float g_mask2[NB * 20 * 20];
// [0..2] = sum(mask) per level, [3..5] = sum((m*(p-t))^2) per level
// zero-initialized at module load; last block of loss kernel re-zeros each run
__device__ double g_acc[6];
__device__ unsigned int g_done;   // completion ticket for loss kernel

// ---------------- helpers ----------------
__device__ __forceinline__ float block_reduce_sum(float v) {
    __shared__ float s[32];
    int lane = threadIdx.x & 31;
    int wid  = threadIdx.x >> 5;
    #pragma unroll
    for (int o = 16; o; o >>= 1) v += __shfl_down_sync(0xffffffffu, v, o);
    if (lane == 0) s[wid] = v;
    __syncthreads();
    int nw = (blockDim.x + 31) >> 5;
    if (wid == 0) {
        v = (lane < nw) ? s[lane] : 0.f;
        #pragma unroll
        for (int o = 16; o; o >>= 1) v += __shfl_down_sync(0xffffffffu, v, o);
    }
    return v;
}

// ---------------- fused mask kernel (all 3 levels, one launch) -------------
// block ranges: [0,400)=L0 (80x80, 25 tiles/img), [400,512)=L1 (40x40, 7 tiles/img),
//               [512,544)=L2 (20x20, 2 tiles/img). 256 threads/block.
__global__ void mask_all_kernel(const float* __restrict__ bboxes,
                                const int*   __restrict__ batch_idx) {
    __shared__ int   s_cnt;
    __shared__ float s_xc[NBOX], s_yc[NBOX], s_iw[NBOX], s_ih[NBOX];
    __shared__ int   s_xl[NBOX], s_xr[NBOX], s_yt[NBOX], s_yd[NBOX];

    const int blk = blockIdx.x;
    int lvl, S, b, tile;
    float* mask;
    if (blk < 400)      { lvl = 0; S = 80; b = blk / 25;        tile = blk % 25;        mask = g_mask0; }
    else if (blk < 512) { lvl = 1; S = 40; b = (blk - 400) / 7; tile = (blk - 400) % 7; mask = g_mask1; }
    else                { lvl = 2; S = 20; b = (blk - 512) / 2; tile = (blk - 512) % 2; mask = g_mask2; }

    if (threadIdx.x == 0) s_cnt = 0;
    __syncthreads();

    // compact this image's boxes into shared, precomputing gaussian params
    if (threadIdx.x < NBOX) {
        int i = threadIdx.x;
        if (batch_idx[i] == b) {
            int j = atomicAdd(&s_cnt, 1);
            float4 bb = reinterpret_cast<const float4*>(bboxes)[i];
            int xc = (int)floorf(bb.x * (float)S);
            int yc = (int)floorf(bb.y * (float)S);
            int w  = (int)floorf(bb.z * (float)S);
            int h  = (int)floorf(bb.w * (float)S);
            int xl = max(xc - w / 2, 0);
            int xr = min(xc + w / 2, S - 1);
            int yt = max(yc - h / 2, 0);
            int yd = min(yc + h / 2, S - 1);
            float width  = (float)(xr - xl + 1);
            float height = (float)(yd - yt + 1);
            // STD=2: STD^2 * (width/2)^2 == width^2 exactly
            s_xc[j] = (float)xc;  s_yc[j] = (float)yc;
            s_iw[j] = 1.0f / (width * width);
            s_ih[j] = 1.0f / (height * height);
            s_xl[j] = xl; s_xr[j] = xr; s_yt[j] = yt; s_yd[j] = yd;
        }
    }
    __syncthreads();

    const int n   = s_cnt;
    const int pix = tile * 256 + threadIdx.x;
    float m = 0.0f;
    if (pix < S * S) {
        int y = pix / S;
        int x = pix - y * S;
        float fx = (float)x, fy = (float)y;
        for (int j = 0; j < n; j++) {
            if (x >= s_xl[j] && x <= s_xr[j] && y >= s_yt[j] && y <= s_yd[j]) {
                float dx = fx - s_xc[j];
                float dy = fy - s_yc[j];
                float e  = __expf(-(dx * dx * s_iw[j] + dy * dy * s_ih[j]));
                m = fmaxf(m, e);
            }
        }
        mask[b * S * S + pix] = m;
    }
    __syncthreads();
    float bs = block_reduce_sum(m);
    if (threadIdx.x == 0 && bs != 0.0f) atomicAdd(&g_acc[lvl], (double)bs);
}

// ---------------- fused loss kernel (all 3 levels + finalize) --------------
template <int CSS, int SS>
__device__ __forceinline__ float loss_partial(const float4* __restrict__ p,
                                              const float4* __restrict__ t,
                                              const float*  __restrict__ mask,
                                              int nvec, int idx, int stride) {
    float acc = 0.0f;
    for (int i = idx; i < nvec; i += stride) {
        float4 pv = p[i];
        float4 tv = t[i];
        int base = i * 4;
        int b    = base / CSS;              // const-div -> mul/shift
        int pix  = base % SS;               // SS | CSS; pix % 4 == 0
        const float4 mv = *reinterpret_cast<const float4*>(&mask[b * SS + pix]);
        float d0 = mv.x * (pv.x - tv.x);
        float d1 = mv.y * (pv.y - tv.y);
        float d2 = mv.z * (pv.z - tv.z);
        float d3 = mv.w * (pv.w - tv.w);
        acc += d0 * d0 + d1 * d1 + d2 * d2 + d3 * d3;
    }
    return acc;
}

// grid = 2960 blocks: [0,1680)=L0, [1680,2520)=L1, [2520,2960)=L2
#define LB0 1680
#define LB1 840
#define LB2 440
#define NBLK (LB0 + LB1 + LB2)

__global__ void loss_all_kernel(const float4* __restrict__ p0, const float4* __restrict__ t0,
                                const float4* __restrict__ p1, const float4* __restrict__ t1,
                                const float4* __restrict__ p2, const float4* __restrict__ t2,
                                float* __restrict__ out) {
    const int blk = blockIdx.x;
    float acc;
    int lvl;
    if (blk < LB0) {
        lvl = 0;
        acc = loss_partial<819200, 6400>(p0, t0, g_mask0, 3276800,
                                         blk * 256 + threadIdx.x, LB0 * 256);
    } else if (blk < LB0 + LB1) {
        lvl = 1;
        acc = loss_partial<409600, 1600>(p1, t1, g_mask1, 1638400,
                                         (blk - LB0) * 256 + threadIdx.x, LB1 * 256);
    } else {
        lvl = 2;
        acc = loss_partial<204800, 400>(p2, t2, g_mask2, 819200,
                                        (blk - LB0 - LB1) * 256 + threadIdx.x, LB2 * 256);
    }

    float bs = block_reduce_sum(acc);
    if (threadIdx.x == 0) {
        atomicAdd(&g_acc[3 + lvl], (double)bs);
        __threadfence();
        unsigned int ticket = atomicAdd(&g_done, 1u);
        if (ticket == NBLK - 1) {
            // last block: all g_acc[3..5] adds are visible (fence+atomic order);
            // g_acc[0..2] completed in the prior kernel.
            __threadfence();
            const double C[3] = {128.0, 256.0, 512.0};
            double total = 0.0;
            #pragma unroll
            for (int l = 0; l < 3; l++)
                total += g_acc[3 + l] / (C[l] * g_acc[l]);
            out[0] = (float)(total / 3.0);
            // reset state for next graph replay (deterministic per-run)
            #pragma unroll
            for (int l = 0; l < 6; l++) g_acc[l] = 0.0;
            g_done = 0u;
        }
    }
}

// ---------------- launch ----------------
extern "C" void kernel_launch(void* const* d_in, const int* in_sizes, int n_in,
                              void* d_out, int out_size) {
    // metadata order (setup_inputs dict insertion order) is INTERLEAVED:
    // [0]=y_pred0 [1]=y_true0 [2]=y_pred1 [3]=y_true1 [4]=y_pred2 [5]=y_true2
    // [6]=bboxes  [7]=cls     [8]=batch_idx
    const float* p0 = (const float*)d_in[0];
    const float* t0 = (const float*)d_in[1];
    const float* p1 = (const float*)d_in[2];
    const float* t1 = (const float*)d_in[3];
    const float* p2 = (const float*)d_in[4];
    const float* t2 = (const float*)d_in[5];
    const float* bboxes = (const float*)d_in[6];
    const int* batch_idx = (const int*)d_in[8];

    mask_all_kernel<<<544, 256>>>(bboxes, batch_idx);

    loss_all_kernel<<<NBLK, 256>>>(
        (const float4*)p0, (const float4*)t0,
        (const float4*)p1, (const float4*)t1,
        (const float4*)p2, (const float4*)t2,
        (float*)d_out);
}

// round 16
// speedup vs baseline: 1.3768x; 1.0021x over previous
#include <cuda_runtime.h>

#define NB 16          // batch
#define NBOX 256       // boxes

// ---------------- device scratch (no allocations allowed) ----------------
__device__ __align__(16) float g_mask0[NB * 80 * 80];
__device__ __align__(16) float g_mask1[NB * 40 * 40];
__device__ __align__(16) float g_mask2[NB * 20 * 20];
// [0..2] = sum(mask) per level, [3..5] = sum((m*(p-t))^2) per level
// zero-initialized at module load; last block of loss kernel re-zeros each run
__device__ double g_acc[6];
__device__ unsigned int g_done;   // completion ticket for loss kernel

// ---------------- helpers ----------------
__device__ __forceinline__ float block_reduce_sum(float v) {
    __shared__ float s[32];
    int lane = threadIdx.x & 31;
    int wid  = threadIdx.x >> 5;
    #pragma unroll
    for (int o = 16; o; o >>= 1) v += __shfl_down_sync(0xffffffffu, v, o);
    if (lane == 0) s[wid] = v;
    __syncthreads();
    int nw = (blockDim.x + 31) >> 5;
    if (wid == 0) {
        v = (lane < nw) ? s[lane] : 0.f;
        #pragma unroll
        for (int o = 16; o; o >>= 1) v += __shfl_down_sync(0xffffffffu, v, o);
    }
    return v;
}

// ---------------- fused mask kernel (all 3 levels, one launch) -------------
// block ranges: [0,400)=L0 (80x80, 25 tiles/img), [400,512)=L1 (40x40, 7 tiles/img),
//               [512,544)=L2 (20x20, 2 tiles/img). 256 threads/block.
__global__ void mask_all_kernel(const float* __restrict__ bboxes,
                                const int*   __restrict__ batch_idx) {
    __shared__ int   s_cnt;
    __shared__ float s_xc[NBOX], s_yc[NBOX], s_iw[NBOX], s_ih[NBOX];
    __shared__ int   s_xl[NBOX], s_xr[NBOX], s_yt[NBOX], s_yd[NBOX];

    const int blk = blockIdx.x;
    int lvl, S, b, tile;
    float* mask;
    if (blk < 400)      { lvl = 0; S = 80; b = blk / 25;        tile = blk % 25;        mask = g_mask0; }
    else if (blk < 512) { lvl = 1; S = 40; b = (blk - 400) / 7; tile = (blk - 400) % 7; mask = g_mask1; }
    else                { lvl = 2; S = 20; b = (blk - 512) / 2; tile = (blk - 512) % 2; mask = g_mask2; }

    if (threadIdx.x == 0) s_cnt = 0;
    __syncthreads();

    // compact this image's boxes into shared, precomputing gaussian params
    if (threadIdx.x < NBOX) {
        int i = threadIdx.x;
        if (batch_idx[i] == b) {
            int j = atomicAdd(&s_cnt, 1);
            float4 bb = reinterpret_cast<const float4*>(bboxes)[i];
            int xc = (int)floorf(bb.x * (float)S);
            int yc = (int)floorf(bb.y * (float)S);
            int w  = (int)floorf(bb.z * (float)S);
            int h  = (int)floorf(bb.w * (float)S);
            int xl = max(xc - w / 2, 0);
            int xr = min(xc + w / 2, S - 1);
            int yt = max(yc - h / 2, 0);
            int yd = min(yc + h / 2, S - 1);
            float width  = (float)(xr - xl + 1);
            float height = (float)(yd - yt + 1);
            // STD=2: STD^2 * (width/2)^2 == width^2 exactly
            s_xc[j] = (float)xc;  s_yc[j] = (float)yc;
            s_iw[j] = 1.0f / (width * width);
            s_ih[j] = 1.0f / (height * height);
            s_xl[j] = xl; s_xr[j] = xr; s_yt[j] = yt; s_yd[j] = yd;
        }
    }
    __syncthreads();

    const int n   = s_cnt;
    const int pix = tile * 256 + threadIdx.x;
    float m = 0.0f;
    if (pix < S * S) {
        int y = pix / S;
        int x = pix - y * S;
        float fx = (float)x, fy = (float)y;
        for (int j = 0; j < n; j++) {
            if (x >= s_xl[j] && x <= s_xr[j] && y >= s_yt[j] && y <= s_yd[j]) {
                float dx = fx - s_xc[j];
                float dy = fy - s_yc[j];
                float e  = __expf(-(dx * dx * s_iw[j] + dy * dy * s_ih[j]));
                m = fmaxf(m, e);
            }
        }
        mask[b * S * S + pix] = m;
    }
    __syncthreads();
    float bs = block_reduce_sum(m);
    if (threadIdx.x == 0 && bs != 0.0f) atomicAdd(&g_acc[lvl], (double)bs);
}

// ---------------- fused loss kernel (all 3 levels + finalize) --------------
// Pair-processing: each thread handles 2 adjacent float4 per iteration with
// independent accumulators (raises front-batched LDGs for latency hiding).
template <int CSS, int SS>
__device__ __forceinline__ float loss_partial(const float4* __restrict__ p,
                                              const float4* __restrict__ t,
                                              const float*  __restrict__ mask,
                                              int npair, int idx, int stride) {
    float acc0 = 0.0f, acc1 = 0.0f;
    for (int i = idx; i < npair; i += stride) {
        int v0 = 2 * i;
        float4 pv0 = p[v0];
        float4 pv1 = p[v0 + 1];
        float4 tv0 = t[v0];
        float4 tv1 = t[v0 + 1];
        int base0 = v0 * 4;
        int b0    = base0 / CSS;            // const-div -> mul/shift
        int pix0  = base0 % SS;             // multiple of 4
        int base1 = base0 + 4;
        int b1    = base1 / CSS;
        int pix1  = base1 % SS;
        float4 mv0 = *reinterpret_cast<const float4*>(&mask[b0 * SS + pix0]);
        float4 mv1 = *reinterpret_cast<const float4*>(&mask[b1 * SS + pix1]);
        float d0 = mv0.x * (pv0.x - tv0.x);
        float d1 = mv0.y * (pv0.y - tv0.y);
        float d2 = mv0.z * (pv0.z - tv0.z);
        float d3 = mv0.w * (pv0.w - tv0.w);
        acc0 += d0 * d0 + d1 * d1 + d2 * d2 + d3 * d3;
        float e0 = mv1.x * (pv1.x - tv1.x);
        float e1 = mv1.y * (pv1.y - tv1.y);
        float e2 = mv1.z * (pv1.z - tv1.z);
        float e3 = mv1.w * (pv1.w - tv1.w);
        acc1 += e0 * e0 + e1 * e1 + e2 * e2 + e3 * e3;
    }
    return acc0 + acc1;
}

// single-wave persistent grid: 148 SMs x 7 blocks = 1036 blocks
// partition [0,588)=L0, [588,882)=L1, [882,1036)=L2  (~bytes-proportional)
#define LB0 588
#define LB1 294
#define LB2 154
#define NBLK (LB0 + LB1 + LB2)

__global__ void __launch_bounds__(256, 7)
loss_all_kernel(const float4* __restrict__ p0, const float4* __restrict__ t0,
                const float4* __restrict__ p1, const float4* __restrict__ t1,
                const float4* __restrict__ p2, const float4* __restrict__ t2,
                float* __restrict__ out) {
    const int blk = blockIdx.x;
    float acc;
    int lvl;
    if (blk < LB0) {
        lvl = 0;   // npair = 3276800/2
        acc = loss_partial<819200, 6400>(p0, t0, g_mask0, 1638400,
                                         blk * 256 + threadIdx.x, LB0 * 256);
    } else if (blk < LB0 + LB1) {
        lvl = 1;   // npair = 1638400/2
        acc = loss_partial<409600, 1600>(p1, t1, g_mask1, 819200,
                                         (blk - LB0) * 256 + threadIdx.x, LB1 * 256);
    } else {
        lvl = 2;   // npair = 819200/2
        acc = loss_partial<204800, 400>(p2, t2, g_mask2, 409600,
                                        (blk - LB0 - LB1) * 256 + threadIdx.x, LB2 * 256);
    }

    float bs = block_reduce_sum(acc);
    if (threadIdx.x == 0) {
        atomicAdd(&g_acc[3 + lvl], (double)bs);
        __threadfence();
        unsigned int ticket = atomicAdd(&g_done, 1u);
        if (ticket == NBLK - 1) {
            // last block: all g_acc[3..5] adds visible (fence+atomic order);
            // g_acc[0..2] completed in the prior kernel (same-stream order).
            __threadfence();
            const double C[3] = {128.0, 256.0, 512.0};
            double total = 0.0;
            #pragma unroll
            for (int l = 0; l < 3; l++)
                total += g_acc[3 + l] / (C[l] * g_acc[l]);
            out[0] = (float)(total / 3.0);
            // reset state for next graph replay (deterministic per-run)
            #pragma unroll
            for (int l = 0; l < 6; l++) g_acc[l] = 0.0;
            g_done = 0u;
        }
    }
}

// ---------------- launch ----------------
extern "C" void kernel_launch(void* const* d_in, const int* in_sizes, int n_in,
                              void* d_out, int out_size) {
    // metadata order (setup_inputs dict insertion order) is INTERLEAVED:
    // [0]=y_pred0 [1]=y_true0 [2]=y_pred1 [3]=y_true1 [4]=y_pred2 [5]=y_true2
    // [6]=bboxes  [7]=cls     [8]=batch_idx
    const float* p0 = (const float*)d_in[0];
    const float* t0 = (const float*)d_in[1];
    const float* p1 = (const float*)d_in[2];
    const float* t1 = (const float*)d_in[3];
    const float* p2 = (const float*)d_in[4];
    const float* t2 = (const float*)d_in[5];
    const float* bboxes = (const float*)d_in[6];
    const int* batch_idx = (const int*)d_in[8];

    mask_all_kernel<<<544, 256>>>(bboxes, batch_idx);

    loss_all_kernel<<<NBLK, 256>>>(
        (const float4*)p0, (const float4*)t0,
        (const float4*)p1, (const float4*)t1,
        (const float4*)p2, (const float4*)t2,
        (float*)d_out);
}

// round 17
// speedup vs baseline: 1.4830x; 1.0772x over previous
#include <cuda_runtime.h>

#define NB 16          // batch
#define NBOX 256       // boxes

// ---------------- device scratch (no allocations allowed) ----------------
__device__ __align__(16) float g_mask0[NB * 80 * 80];
__device__ __align__(16) float g_mask1[NB * 40 * 40];
__device__ __align__(16) float g_mask2[NB * 20 * 20];
// [0..2] = sum(mask) per level, [3..5] = sum((m*(p-t))^2) per level
// zero-initialized at module load; last block of loss kernel re-zeros each run
__device__ double g_acc[6];
__device__ unsigned int g_done;   // completion ticket for loss kernel

// ---------------- helpers ----------------
__device__ __forceinline__ float block_reduce_sum(float v) {
    __shared__ float s[32];
    int lane = threadIdx.x & 31;
    int wid  = threadIdx.x >> 5;
    #pragma unroll
    for (int o = 16; o; o >>= 1) v += __shfl_down_sync(0xffffffffu, v, o);
    if (lane == 0) s[wid] = v;
    __syncthreads();
    int nw = (blockDim.x + 31) >> 5;
    if (wid == 0) {
        v = (lane < nw) ? s[lane] : 0.f;
        #pragma unroll
        for (int o = 16; o; o >>= 1) v += __shfl_down_sync(0xffffffffu, v, o);
    }
    return v;
}

// ---------------- fused mask kernel (all 3 levels, one launch) -------------
// block ranges: [0,400)=L0 (80x80, 25 tiles/img), [400,512)=L1 (40x40, 7 tiles/img),
//               [512,544)=L2 (20x20, 2 tiles/img). 256 threads/block.
__global__ void mask_all_kernel(const float* __restrict__ bboxes,
                                const int*   __restrict__ batch_idx) {
    __shared__ int   s_cnt;
    __shared__ float s_xc[NBOX], s_yc[NBOX], s_iw[NBOX], s_ih[NBOX];
    __shared__ int   s_xl[NBOX], s_xr[NBOX], s_yt[NBOX], s_yd[NBOX];

    const int blk = blockIdx.x;
    int lvl, S, b, tile;
    float* mask;
    if (blk < 400)      { lvl = 0; S = 80; b = blk / 25;        tile = blk % 25;        mask = g_mask0; }
    else if (blk < 512) { lvl = 1; S = 40; b = (blk - 400) / 7; tile = (blk - 400) % 7; mask = g_mask1; }
    else                { lvl = 2; S = 20; b = (blk - 512) / 2; tile = (blk - 512) % 2; mask = g_mask2; }

    if (threadIdx.x == 0) s_cnt = 0;
    __syncthreads();

    // compact this image's boxes into shared, precomputing gaussian params
    if (threadIdx.x < NBOX) {
        int i = threadIdx.x;
        if (batch_idx[i] == b) {
            int j = atomicAdd(&s_cnt, 1);
            float4 bb = reinterpret_cast<const float4*>(bboxes)[i];
            int xc = (int)floorf(bb.x * (float)S);
            int yc = (int)floorf(bb.y * (float)S);
            int w  = (int)floorf(bb.z * (float)S);
            int h  = (int)floorf(bb.w * (float)S);
            int xl = max(xc - w / 2, 0);
            int xr = min(xc + w / 2, S - 1);
            int yt = max(yc - h / 2, 0);
            int yd = min(yc + h / 2, S - 1);
            float width  = (float)(xr - xl + 1);
            float height = (float)(yd - yt + 1);
            // STD=2: STD^2 * (width/2)^2 == width^2 exactly
            s_xc[j] = (float)xc;  s_yc[j] = (float)yc;
            s_iw[j] = 1.0f / (width * width);
            s_ih[j] = 1.0f / (height * height);
            s_xl[j] = xl; s_xr[j] = xr; s_yt[j] = yt; s_yd[j] = yd;
        }
    }
    __syncthreads();

    const int n   = s_cnt;
    const int pix = tile * 256 + threadIdx.x;
    float m = 0.0f;
    if (pix < S * S) {
        int y = pix / S;
        int x = pix - y * S;
        float fx = (float)x, fy = (float)y;
        for (int j = 0; j < n; j++) {
            if (x >= s_xl[j] && x <= s_xr[j] && y >= s_yt[j] && y <= s_yd[j]) {
                float dx = fx - s_xc[j];
                float dy = fy - s_yc[j];
                float e  = __expf(-(dx * dx * s_iw[j] + dy * dy * s_ih[j]));
                m = fmaxf(m, e);
            }
        }
        mask[b * S * S + pix] = m;
    }
    __syncthreads();
    float bs = block_reduce_sum(m);
    if (threadIdx.x == 0 && bs != 0.0f) atomicAdd(&g_acc[lvl], (double)bs);
}

// ---------------- fused loss kernel (all 3 levels + finalize) --------------
// Pair-processing with streaming (evict-first) loads for read-once p/t so L1
// stays dedicated to the hot mask arrays.
template <int CSS, int SS>
__device__ __forceinline__ float loss_partial(const float4* __restrict__ p,
                                              const float4* __restrict__ t,
                                              const float*  __restrict__ mask,
                                              int npair, int idx, int stride) {
    float acc0 = 0.0f, acc1 = 0.0f;
    for (int i = idx; i < npair; i += stride) {
        int v0 = 2 * i;
        float4 pv0 = __ldcs(&p[v0]);
        float4 pv1 = __ldcs(&p[v0 + 1]);
        float4 tv0 = __ldcs(&t[v0]);
        float4 tv1 = __ldcs(&t[v0 + 1]);
        int base0 = v0 * 4;
        int b0    = base0 / CSS;            // const-div -> mul/shift
        int pix0  = base0 % SS;             // multiple of 4
        int base1 = base0 + 4;
        int b1    = base1 / CSS;
        int pix1  = base1 % SS;
        float4 mv0 = *reinterpret_cast<const float4*>(&mask[b0 * SS + pix0]);
        float4 mv1 = *reinterpret_cast<const float4*>(&mask[b1 * SS + pix1]);
        float d0 = mv0.x * (pv0.x - tv0.x);
        float d1 = mv0.y * (pv0.y - tv0.y);
        float d2 = mv0.z * (pv0.z - tv0.z);
        float d3 = mv0.w * (pv0.w - tv0.w);
        acc0 += d0 * d0 + d1 * d1 + d2 * d2 + d3 * d3;
        float e0 = mv1.x * (pv1.x - tv1.x);
        float e1 = mv1.y * (pv1.y - tv1.y);
        float e2 = mv1.z * (pv1.z - tv1.z);
        float e3 = mv1.w * (pv1.w - tv1.w);
        acc1 += e0 * e0 + e1 * e1 + e2 * e2 + e3 * e3;
    }
    return acc0 + acc1;
}

// single-wave persistent grid: 148 SMs x 8 blocks = 1184 blocks
// partition [0,672)=L0, [672,1008)=L1, [1008,1184)=L2 (~bytes-proportional)
#define LB0 672
#define LB1 336
#define LB2 176
#define NBLK (LB0 + LB1 + LB2)

__global__ void __launch_bounds__(256, 8)
loss_all_kernel(const float4* __restrict__ p0, const float4* __restrict__ t0,
                const float4* __restrict__ p1, const float4* __restrict__ t1,
                const float4* __restrict__ p2, const float4* __restrict__ t2,
                float* __restrict__ out) {
    const int blk = blockIdx.x;
    float acc;
    int lvl;
    if (blk < LB0) {
        lvl = 0;   // npair = 3276800/2
        acc = loss_partial<819200, 6400>(p0, t0, g_mask0, 1638400,
                                         blk * 256 + threadIdx.x, LB0 * 256);
    } else if (blk < LB0 + LB1) {
        lvl = 1;   // npair = 1638400/2
        acc = loss_partial<409600, 1600>(p1, t1, g_mask1, 819200,
                                         (blk - LB0) * 256 + threadIdx.x, LB1 * 256);
    } else {
        lvl = 2;   // npair = 819200/2
        acc = loss_partial<204800, 400>(p2, t2, g_mask2, 409600,
                                        (blk - LB0 - LB1) * 256 + threadIdx.x, LB2 * 256);
    }

    float bs = block_reduce_sum(acc);
    if (threadIdx.x == 0) {
        atomicAdd(&g_acc[3 + lvl], (double)bs);
        __threadfence();
        unsigned int ticket = atomicAdd(&g_done, 1u);
        if (ticket == NBLK - 1) {
            // last block: all g_acc[3..5] adds visible (fence+atomic order);
            // g_acc[0..2] completed in the prior kernel (same-stream order).
            __threadfence();
            const double C[3] = {128.0, 256.0, 512.0};
            double total = 0.0;
            #pragma unroll
            for (int l = 0; l < 3; l++)
                total += g_acc[3 + l] / (C[l] * g_acc[l]);
            out[0] = (float)(total / 3.0);
            // reset state for next graph replay (deterministic per-run)
            #pragma unroll
            for (int l = 0; l < 6; l++) g_acc[l] = 0.0;
            g_done = 0u;
        }
    }
}

// ---------------- launch ----------------
extern "C" void kernel_launch(void* const* d_in, const int* in_sizes, int n_in,
                              void* d_out, int out_size) {
    // metadata order (setup_inputs dict insertion order) is INTERLEAVED:
    // [0]=y_pred0 [1]=y_true0 [2]=y_pred1 [3]=y_true1 [4]=y_pred2 [5]=y_true2
    // [6]=bboxes  [7]=cls     [8]=batch_idx
    const float* p0 = (const float*)d_in[0];
    const float* t0 = (const float*)d_in[1];
    const float* p1 = (const float*)d_in[2];
    const float* t1 = (const float*)d_in[3];
    const float* p2 = (const float*)d_in[4];
    const float* t2 = (const float*)d_in[5];
    const float* bboxes = (const float*)d_in[6];
    const int* batch_idx = (const int*)d_in[8];

    mask_all_kernel<<<544, 256>>>(bboxes, batch_idx);

    loss_all_kernel<<<NBLK, 256>>>(
        (const float4*)p0, (const float4*)t0,
        (const float4*)p1, (const float4*)t1,
        (const float4*)p2, (const float4*)t2,
        (float*)d_out);
}